// round 7
// baseline (speedup 1.0000x reference)
#include <cuda_runtime.h>
#include <cstdint>

#define MARGIN 1.0f
#define MAX_TRIALS 50
#define P1_TRIALS 2
#define BLK 256
#define MAX_B (1 << 20)
#define MAX_NB ((MAX_B + BLK - 1) / BLK)   // 4096

// Scratch (no allocations allowed in kernel_launch)
__device__ float g_neg_score[MAX_B];   // scores of label-0 examples, stable order
__device__ float g_pos_score[MAX_B];   // scores of label-1 examples, stable order
__device__ int   g_pos_idx[MAX_B];     // original indices of label-1 examples
__device__ int   g_queue[MAX_B];       // unresolved positive slots
__device__ int   g_blockcnt[MAX_NB];
__device__ float g_partials[MAX_NB];
__device__ int   g_num_neg;
__device__ int   g_qcount;
__device__ float g_extra;
__device__ float g_harm[MAX_TRIALS];

// ---------------- Threefry-2x32 (exact JAX partitionable semantics) --------
__device__ __forceinline__ uint32_t rotl32(uint32_t x, int d) {
    return __funnelshift_l(x, x, d);
}

__device__ __forceinline__ uint32_t jax_random_bits32(uint32_t j) {
    const uint32_t k0 = 0u, k1 = 42u;
    const uint32_t ks2 = k0 ^ k1 ^ 0x1BD11BDAu;
    uint32_t x0 = 0u + k0;          // c0 = hi32(j) = 0
    uint32_t x1 = j + k1;           // c1 = lo32(j)
    const int R0[4] = {13, 15, 26, 6};
    const int R1[4] = {17, 29, 16, 24};
#pragma unroll
    for (int i = 0; i < 4; i++) { x0 += x1; x1 = rotl32(x1, R0[i]); x1 ^= x0; }
    x0 += k1;  x1 += ks2 + 1u;
#pragma unroll
    for (int i = 0; i < 4; i++) { x0 += x1; x1 = rotl32(x1, R1[i]); x1 ^= x0; }
    x0 += ks2; x1 += k0 + 2u;
#pragma unroll
    for (int i = 0; i < 4; i++) { x0 += x1; x1 = rotl32(x1, R0[i]); x1 ^= x0; }
    x0 += k0;  x1 += k1 + 3u;
#pragma unroll
    for (int i = 0; i < 4; i++) { x0 += x1; x1 = rotl32(x1, R1[i]); x1 ^= x0; }
    x0 += k1;  x1 += ks2 + 4u;
#pragma unroll
    for (int i = 0; i < 4; i++) { x0 += x1; x1 = rotl32(x1, R0[i]); x1 ^= x0; }
    x0 += ks2; x1 += k0 + 5u;
    return x0 ^ x1;
}

__device__ __forceinline__ float bits_to_uniform(uint32_t bits) {
    return __uint_as_float((bits >> 9) | 0x3f800000u) - 1.0f;
}

__device__ __forceinline__ float sample_neg(uint32_t j, float nnf, int num_neg) {
    float u = bits_to_uniform(jax_random_bits32(j));
    int idx = (int)(u * nnf);
    idx = min(max(idx, 0), num_neg - 1);
    return __ldg(&g_neg_score[idx]);
}

// ---------------- Pass 1: per-block count of label==0 ----------------
__global__ void count_zeros_kernel(const int* __restrict__ labels, int B) {
    int i = blockIdx.x * BLK + threadIdx.x;
    int f = (i < B && labels[i] == 0) ? 1 : 0;
    unsigned m = __ballot_sync(0xffffffffu, f);
    __shared__ int wsum[BLK / 32];
    if ((threadIdx.x & 31) == 0) wsum[threadIdx.x >> 5] = __popc(m);
    __syncthreads();
    if (threadIdx.x == 0) {
        int s = 0;
#pragma unroll
        for (int w = 0; w < BLK / 32; w++) s += wsum[w];
        g_blockcnt[blockIdx.x] = s;
    }
}

// ---------------- Pass 2: exclusive scan + per-replay init -----------------
__global__ void scan_blocks_kernel(int nb) {
    __shared__ int sh[1024];
    int t = threadIdx.x;
    int v[4];
    int base = t * 4;
    int s = 0;
#pragma unroll
    for (int k = 0; k < 4; k++) {
        int idx = base + k;
        v[k] = (idx < nb) ? g_blockcnt[idx] : 0;
        s += v[k];
    }
    sh[t] = s;
    __syncthreads();
    for (int off = 1; off < 1024; off <<= 1) {
        int y = (t >= off) ? sh[t - off] : 0;
        __syncthreads();
        sh[t] += y;
        __syncthreads();
    }
    int run = (t > 0) ? sh[t - 1] : 0;
#pragma unroll
    for (int k = 0; k < 4; k++) {
        int idx = base + k;
        if (idx < nb) {
            int c = v[k];
            g_blockcnt[idx] = run;
            run += c;
        }
    }
    if (t == 0) {
        g_num_neg = sh[1023];
        g_qcount = 0;
        g_extra = 0.0f;
        float h = 0.0f;
#pragma unroll
        for (int j = 1; j <= MAX_TRIALS; j++) {
            h += __fdiv_rn(1.0f, (float)j);
            g_harm[j - 1] = h;
        }
    }
}

// ---------------- Pass 3: scatter neg scores + pos (idx,score), stable -----
__global__ void scatter_kernel(const int* __restrict__ labels,
                               const float* __restrict__ scores, int B) {
    int i = blockIdx.x * BLK + threadIdx.x;
    int lane = threadIdx.x & 31;
    int w = threadIdx.x >> 5;
    int   lab = (i < B) ? labels[i] : 1;
    float sc  = (i < B) ? scores[i] : 0.0f;
    int f = (i < B && lab == 0) ? 1 : 0;
    unsigned m = __ballot_sync(0xffffffffu, f);
    int wr = __popc(m & ((1u << lane) - 1u));
    __shared__ int woff[BLK / 32];
    if (lane == 0) woff[w] = __popc(m);
    __syncthreads();
    if (threadIdx.x == 0) {
        int r = 0;
#pragma unroll
        for (int k = 0; k < BLK / 32; k++) { int c = woff[k]; woff[k] = r; r += c; }
    }
    __syncthreads();
    if (i < B) {
        int neg_before = g_blockcnt[blockIdx.x] + woff[w] + wr;  // negs strictly before i
        if (f) {
            g_neg_score[neg_before] = sc;
        } else {
            int ps = i - neg_before;
            g_pos_idx[ps] = i;
            g_pos_score[ps] = sc;
        }
    }
}

// ---------------- Phase 1: 2 trials + warp-agg enqueue + fused reduction ---
__global__ void phase1_kernel(int B) {
    __shared__ float red[BLK];
    int tid = threadIdx.x;
    int lane = tid & 31;
    int p = blockIdx.x * BLK + tid;
    int num_neg = g_num_neg;
    int num_pos = B - num_neg;

    float per = 0.0f;
    bool need_enqueue = false;
    if (p < num_pos && num_neg > 0) {
        int i = g_pos_idx[p];
        float s = g_pos_score[p];
        float nnf = (float)num_neg;
        uint32_t jb = (uint32_t)i * (uint32_t)MAX_TRIALS;

        float ns[P1_TRIALS];
#pragma unroll
        for (int k = 0; k < P1_TRIALS; k++)
            ns[k] = sample_neg(jb + (uint32_t)k, nnf, num_neg);

        bool resolved = false;
#pragma unroll
        for (int k = 0; k < P1_TRIALS; k++) {
            if (!resolved && ns[k] + MARGIN > s) {
                int rank = max(1, MAX_TRIALS / (k + 1));
                per = __ldg(&g_harm[rank - 1]) * fmaxf(MARGIN - (s - ns[k]), 0.0f);
                resolved = true;
            }
        }
        need_enqueue = !resolved;
    }

    // warp-aggregated enqueue: ONE atomic per warp instead of one per lane
    unsigned mask = __ballot_sync(0xffffffffu, need_enqueue);
    if (mask) {
        int leader = __ffs(mask) - 1;
        int base = 0;
        if (lane == leader) base = atomicAdd(&g_qcount, __popc(mask));
        base = __shfl_sync(0xffffffffu, base, leader);
        if (need_enqueue)
            g_queue[base + __popc(mask & ((1u << lane) - 1u))] = p;
    }

    // deterministic in-block reduction of resolved contributions
    red[tid] = per;
    __syncthreads();
    for (int off = BLK / 2; off > 0; off >>= 1) {
        if (tid < off) red[tid] += red[tid + off];
        __syncthreads();
    }
    if (tid == 0) g_partials[blockIdx.x] = red[0];
}

// ---------------- Phase 2: trials 2..49 for unresolved (dense) -------------
__global__ void phase2_kernel() {
    int n = g_qcount;
    int num_neg = g_num_neg;
    float nnf = (float)num_neg;
    float acc = 0.0f;
    for (int q = blockIdx.x * blockDim.x + threadIdx.x; q < n;
         q += gridDim.x * blockDim.x) {
        int p = g_queue[q];
        int i = g_pos_idx[p];
        float s = g_pos_score[p];
        uint32_t jb = (uint32_t)i * (uint32_t)MAX_TRIALS;
        bool done = false;
#pragma unroll 1
        for (int tb = P1_TRIALS; tb < MAX_TRIALS && !done; tb += 4) {
            float ns[4];
            int nk = min(4, MAX_TRIALS - tb);
#pragma unroll
            for (int k = 0; k < 4; k++)
                if (k < nk) ns[k] = sample_neg(jb + (uint32_t)(tb + k), nnf, num_neg);
#pragma unroll
            for (int k = 0; k < 4; k++) {
                if (!done && k < nk && ns[k] + MARGIN > s) {
                    int t = tb + k;
                    int rank = max(1, MAX_TRIALS / (t + 1));
                    acc += __ldg(&g_harm[rank - 1]) * fmaxf(MARGIN - (s - ns[k]), 0.0f);
                    done = true;
                }
            }
        }
    }
    // warp-reduce then one atomic per warp
#pragma unroll
    for (int off = 16; off > 0; off >>= 1)
        acc += __shfl_down_sync(0xffffffffu, acc, off);
    if ((threadIdx.x & 31) == 0 && acc != 0.0f) atomicAdd(&g_extra, acc);
}

// ---------------- Finalize -------------------------------------------------
__global__ void finalize_kernel(float* __restrict__ out, int nb, int B) {
    __shared__ float red[1024];
    float s = 0.0f;
    for (int k = threadIdx.x; k < nb; k += 1024) s += g_partials[k];
    red[threadIdx.x] = s;
    __syncthreads();
    for (int off = 512; off > 0; off >>= 1) {
        if (threadIdx.x < off) red[threadIdx.x] += red[threadIdx.x + off];
        __syncthreads();
    }
    if (threadIdx.x == 0) {
        int nn = g_num_neg;
        int np = B - nn;
        float total = red[0] + g_extra;
        out[0] = (nn > 0 && np > 0) ? total / (float)np : 0.0f;
    }
}

extern "C" void kernel_launch(void* const* d_in, const int* in_sizes, int n_in,
                              void* d_out, int out_size) {
    const float* scores = (const float*)d_in[0];
    const int*   labels = (const int*)d_in[1];
    float* out = (float*)d_out;
    int B  = in_sizes[0];
    int nb = (B + BLK - 1) / BLK;

    count_zeros_kernel<<<nb, BLK>>>(labels, B);
    scan_blocks_kernel<<<1, 1024>>>(nb);
    scatter_kernel<<<nb, BLK>>>(labels, scores, B);
    phase1_kernel<<<nb, BLK>>>(B);
    phase2_kernel<<<296, BLK>>>();
    finalize_kernel<<<1, 1024>>>(out, nb, B);
}

// round 8
// speedup vs baseline: 1.1049x; 1.1049x over previous
#include <cuda_runtime.h>
#include <cstdint>

#define MARGIN 1.0f
#define MAX_TRIALS 50
#define BLK 256
#define MAX_B (1 << 20)
#define MAX_NB ((MAX_B + BLK - 1) / BLK)   // 4096

// Scratch (no allocations allowed in kernel_launch)
__device__ float g_neg_score[MAX_B];   // scores of label-0 examples, stable order
__device__ float g_pos_score[MAX_B];   // scores of label-1 examples, stable order
__device__ int   g_pos_idx[MAX_B];     // original indices of label-1 examples
__device__ int   g_queue[MAX_B];       // unresolved after trial 0
__device__ int   g_queue2[MAX_B];      // unresolved after trial 8
__device__ int   g_blockcnt[MAX_NB];
__device__ float g_partials[MAX_NB];
__device__ int   g_num_neg;
__device__ int   g_qcount;
__device__ int   g_qcount2;
__device__ float g_extra;
__device__ float g_harm[MAX_TRIALS];

// ---------------- Threefry-2x32 (exact JAX partitionable semantics) --------
__device__ __forceinline__ uint32_t rotl32(uint32_t x, int d) {
    return __funnelshift_l(x, x, d);
}

__device__ __forceinline__ uint32_t jax_random_bits32(uint32_t j) {
    const uint32_t k0 = 0u, k1 = 42u;
    const uint32_t ks2 = k0 ^ k1 ^ 0x1BD11BDAu;
    uint32_t x0 = 0u + k0;          // c0 = hi32(j) = 0
    uint32_t x1 = j + k1;           // c1 = lo32(j)
    const int R0[4] = {13, 15, 26, 6};
    const int R1[4] = {17, 29, 16, 24};
#pragma unroll
    for (int i = 0; i < 4; i++) { x0 += x1; x1 = rotl32(x1, R0[i]); x1 ^= x0; }
    x0 += k1;  x1 += ks2 + 1u;
#pragma unroll
    for (int i = 0; i < 4; i++) { x0 += x1; x1 = rotl32(x1, R1[i]); x1 ^= x0; }
    x0 += ks2; x1 += k0 + 2u;
#pragma unroll
    for (int i = 0; i < 4; i++) { x0 += x1; x1 = rotl32(x1, R0[i]); x1 ^= x0; }
    x0 += k0;  x1 += k1 + 3u;
#pragma unroll
    for (int i = 0; i < 4; i++) { x0 += x1; x1 = rotl32(x1, R1[i]); x1 ^= x0; }
    x0 += k1;  x1 += ks2 + 4u;
#pragma unroll
    for (int i = 0; i < 4; i++) { x0 += x1; x1 = rotl32(x1, R0[i]); x1 ^= x0; }
    x0 += ks2; x1 += k0 + 5u;
    return x0 ^ x1;
}

__device__ __forceinline__ float bits_to_uniform(uint32_t bits) {
    return __uint_as_float((bits >> 9) | 0x3f800000u) - 1.0f;
}

__device__ __forceinline__ float sample_neg(uint32_t j, float nnf, int num_neg) {
    float u = bits_to_uniform(jax_random_bits32(j));
    int idx = (int)(u * nnf);
    idx = min(max(idx, 0), num_neg - 1);
    return __ldg(&g_neg_score[idx]);
}

// ---------------- Pass 1: per-block count of label==0 ----------------
__global__ void count_zeros_kernel(const int* __restrict__ labels, int B) {
    int i = blockIdx.x * BLK + threadIdx.x;
    int f = (i < B && labels[i] == 0) ? 1 : 0;
    unsigned m = __ballot_sync(0xffffffffu, f);
    __shared__ int wsum[BLK / 32];
    if ((threadIdx.x & 31) == 0) wsum[threadIdx.x >> 5] = __popc(m);
    __syncthreads();
    if (threadIdx.x == 0) {
        int s = 0;
#pragma unroll
        for (int w = 0; w < BLK / 32; w++) s += wsum[w];
        g_blockcnt[blockIdx.x] = s;
    }
}

// ---------------- Pass 2: exclusive scan + per-replay init -----------------
__global__ void scan_blocks_kernel(int nb) {
    __shared__ int sh[1024];
    int t = threadIdx.x;
    int v[4];
    int base = t * 4;
    int s = 0;
#pragma unroll
    for (int k = 0; k < 4; k++) {
        int idx = base + k;
        v[k] = (idx < nb) ? g_blockcnt[idx] : 0;
        s += v[k];
    }
    sh[t] = s;
    __syncthreads();
    for (int off = 1; off < 1024; off <<= 1) {
        int y = (t >= off) ? sh[t - off] : 0;
        __syncthreads();
        sh[t] += y;
        __syncthreads();
    }
    int run = (t > 0) ? sh[t - 1] : 0;
#pragma unroll
    for (int k = 0; k < 4; k++) {
        int idx = base + k;
        if (idx < nb) {
            int c = v[k];
            g_blockcnt[idx] = run;
            run += c;
        }
    }
    if (t == 0) {
        g_num_neg = sh[1023];
        g_qcount = 0;
        g_qcount2 = 0;
        g_extra = 0.0f;
        float h = 0.0f;
#pragma unroll
        for (int j = 1; j <= MAX_TRIALS; j++) {
            h += __fdiv_rn(1.0f, (float)j);
            g_harm[j - 1] = h;
        }
    }
}

// ---------------- Pass 3: scatter neg scores + pos (idx,score), stable -----
__global__ void scatter_kernel(const int* __restrict__ labels,
                               const float* __restrict__ scores, int B) {
    int i = blockIdx.x * BLK + threadIdx.x;
    int lane = threadIdx.x & 31;
    int w = threadIdx.x >> 5;
    int   lab = (i < B) ? labels[i] : 1;
    float sc  = (i < B) ? scores[i] : 0.0f;
    int f = (i < B && lab == 0) ? 1 : 0;
    unsigned m = __ballot_sync(0xffffffffu, f);
    int wr = __popc(m & ((1u << lane) - 1u));
    __shared__ int woff[BLK / 32];
    if (lane == 0) woff[w] = __popc(m);
    __syncthreads();
    if (threadIdx.x == 0) {
        int r = 0;
#pragma unroll
        for (int k = 0; k < BLK / 32; k++) { int c = woff[k]; woff[k] = r; r += c; }
    }
    __syncthreads();
    if (i < B) {
        int neg_before = g_blockcnt[blockIdx.x] + woff[w] + wr;  // negs strictly before i
        if (f) {
            g_neg_score[neg_before] = sc;
        } else {
            int ps = i - neg_before;
            g_pos_idx[ps] = i;
            g_pos_score[ps] = sc;
        }
    }
}

// ---------------- Phase 1: trial 0 only + warp-agg enqueue + reduction -----
__global__ void phase1_kernel(int B) {
    __shared__ float red[BLK];
    int tid = threadIdx.x;
    int lane = tid & 31;
    int num_neg = g_num_neg;
    int num_pos = B - num_neg;

    if (blockIdx.x * BLK >= num_pos) {       // whole block out of range
        if (tid == 0) g_partials[blockIdx.x] = 0.0f;
        return;
    }

    int p = blockIdx.x * BLK + tid;
    float per = 0.0f;
    bool need_enqueue = false;
    if (p < num_pos && num_neg > 0) {
        int i = g_pos_idx[p];
        float s = g_pos_score[p];
        float nnf = (float)num_neg;
        uint32_t jb = (uint32_t)i * (uint32_t)MAX_TRIALS;
        float ns = sample_neg(jb, nnf, num_neg);
        if (ns + MARGIN > s) {
            // t = 0 -> rank = 50 -> harm[49]
            per = __ldg(&g_harm[MAX_TRIALS - 1]) * fmaxf(MARGIN - (s - ns), 0.0f);
        } else {
            need_enqueue = true;
        }
    }

    unsigned mask = __ballot_sync(0xffffffffu, need_enqueue);
    if (mask) {
        int leader = __ffs(mask) - 1;
        int base = 0;
        if (lane == leader) base = atomicAdd(&g_qcount, __popc(mask));
        base = __shfl_sync(0xffffffffu, base, leader);
        if (need_enqueue)
            g_queue[base + __popc(mask & ((1u << lane) - 1u))] = p;
    }

    red[tid] = per;
    __syncthreads();
    for (int off = BLK / 2; off > 0; off >>= 1) {
        if (tid < off) red[tid] += red[tid + off];
        __syncthreads();
    }
    if (tid == 0) g_partials[blockIdx.x] = red[0];
}

// ---------------- Phase 2: trials 1..8 (batch-4, early exit) ---------------
__global__ void phase2_kernel() {
    __shared__ float red[BLK];
    int n = g_qcount;
    int num_neg = g_num_neg;
    float nnf = (float)num_neg;
    int tid = threadIdx.x;
    int lane = tid & 31;
    float acc = 0.0f;
    for (int q = blockIdx.x * blockDim.x + tid; q < n;
         q += gridDim.x * blockDim.x) {
        int p = g_queue[q];
        int i = g_pos_idx[p];
        float s = g_pos_score[p];
        uint32_t jb = (uint32_t)i * (uint32_t)MAX_TRIALS;
        bool done = false;
#pragma unroll
        for (int tb = 1; tb < 9; tb += 4) {
            if (done) continue;
            float ns[4];
#pragma unroll
            for (int k = 0; k < 4; k++)
                ns[k] = sample_neg(jb + (uint32_t)(tb + k), nnf, num_neg);
#pragma unroll
            for (int k = 0; k < 4; k++) {
                if (!done && ns[k] + MARGIN > s) {
                    int t = tb + k;
                    int rank = max(1, MAX_TRIALS / (t + 1));
                    acc += __ldg(&g_harm[rank - 1]) * fmaxf(MARGIN - (s - ns[k]), 0.0f);
                    done = true;
                }
            }
        }
        // survivors of trials 0..8 -> queue B (warp-aggregated)
        unsigned mask = __ballot_sync(__activemask(), !done);
        if (!done) {
            int leader = __ffs(mask) - 1;
            int base = 0;
            if (lane == leader) base = atomicAdd(&g_qcount2, __popc(mask));
            base = __shfl_sync(mask, base, leader);
            g_queue2[base + __popc(mask & ((1u << lane) - 1u))] = p;
        }
    }
    red[tid] = acc;
    __syncthreads();
    for (int off = BLK / 2; off > 0; off >>= 1) {
        if (tid < off) red[tid] += red[tid + off];
        __syncthreads();
    }
    if (tid == 0 && red[0] != 0.0f) atomicAdd(&g_extra, red[0]);
}

// ---------------- Phase 3: one warp per heavy item, lane-parallel trials ---
__global__ void phase3_kernel() {
    __shared__ float red[BLK];
    int n = g_qcount2;
    int num_neg = g_num_neg;
    float nnf = (float)num_neg;
    int tid = threadIdx.x;
    int lane = tid & 31;
    int gw = (blockIdx.x * blockDim.x + tid) >> 5;
    int nwarps = (gridDim.x * blockDim.x) >> 5;
    float acc = 0.0f;
    for (int q = gw; q < n; q += nwarps) {
        int p = g_queue2[q];
        int i = g_pos_idx[p];
        float s = g_pos_score[p];
        uint32_t jb = (uint32_t)i * (uint32_t)MAX_TRIALS;

        // round 1: trials 9..40, one per lane
        int t1 = 9 + lane;
        float ns1 = sample_neg(jb + (uint32_t)t1, nnf, num_neg);
        bool v1 = (ns1 + MARGIN > s);
        unsigned m1 = __ballot_sync(0xffffffffu, v1);
        int hit_t = -1;
        float hit_ns = 0.0f;
        if (m1) {
            int lead = __ffs(m1) - 1;
            hit_t = 9 + lead;
            hit_ns = __shfl_sync(0xffffffffu, ns1, lead);
        } else {
            // round 2: trials 41..49, lanes 0..8
            int t2 = 41 + lane;
            bool act = (t2 < MAX_TRIALS);
            float ns2 = act ? sample_neg(jb + (uint32_t)t2, nnf, num_neg) : 0.0f;
            bool v2 = act && (ns2 + MARGIN > s);
            unsigned m2 = __ballot_sync(0xffffffffu, v2);
            if (m2) {
                int lead = __ffs(m2) - 1;
                hit_t = 41 + lead;
                hit_ns = __shfl_sync(0xffffffffu, ns2, lead);
            }
        }
        if (lane == 0 && hit_t >= 0) {
            int rank = max(1, MAX_TRIALS / (hit_t + 1));
            acc += __ldg(&g_harm[rank - 1]) * fmaxf(MARGIN - (s - hit_ns), 0.0f);
        }
    }
    red[tid] = acc;
    __syncthreads();
    for (int off = BLK / 2; off > 0; off >>= 1) {
        if (tid < off) red[tid] += red[tid + off];
        __syncthreads();
    }
    if (tid == 0 && red[0] != 0.0f) atomicAdd(&g_extra, red[0]);
}

// ---------------- Finalize -------------------------------------------------
__global__ void finalize_kernel(float* __restrict__ out, int nb, int B) {
    __shared__ float red[1024];
    float s = 0.0f;
    for (int k = threadIdx.x; k < nb; k += 1024) s += g_partials[k];
    red[threadIdx.x] = s;
    __syncthreads();
    for (int off = 512; off > 0; off >>= 1) {
        if (threadIdx.x < off) red[threadIdx.x] += red[threadIdx.x + off];
        __syncthreads();
    }
    if (threadIdx.x == 0) {
        int nn = g_num_neg;
        int np = B - nn;
        float total = red[0] + g_extra;
        out[0] = (nn > 0 && np > 0) ? total / (float)np : 0.0f;
    }
}

extern "C" void kernel_launch(void* const* d_in, const int* in_sizes, int n_in,
                              void* d_out, int out_size) {
    const float* scores = (const float*)d_in[0];
    const int*   labels = (const int*)d_in[1];
    float* out = (float*)d_out;
    int B  = in_sizes[0];
    int nb = (B + BLK - 1) / BLK;

    count_zeros_kernel<<<nb, BLK>>>(labels, B);
    scan_blocks_kernel<<<1, 1024>>>(nb);
    scatter_kernel<<<nb, BLK>>>(labels, scores, B);
    phase1_kernel<<<nb, BLK>>>(B);
    phase2_kernel<<<592, BLK>>>();
    phase3_kernel<<<592, BLK>>>();
    finalize_kernel<<<1, 1024>>>(out, nb, B);
}

// round 9
// speedup vs baseline: 1.1608x; 1.0506x over previous
#include <cuda_runtime.h>
#include <cstdint>

#define MARGIN 1.0f
#define MAX_TRIALS 50
#define BLK 256
#define MAIN_GRID 592
#define MAX_B (1 << 20)
#define MAX_NB ((MAX_B + BLK - 1) / BLK)   // 4096

// Scratch (no allocations allowed in kernel_launch)
__device__ float g_neg_score[MAX_B];   // scores of label-0 examples, stable order
__device__ float g_pos_score[MAX_B];   // scores of label-1 examples, stable order
__device__ int   g_pos_idx[MAX_B];     // original indices of label-1 examples
__device__ int   g_blockcnt[MAX_NB];
__device__ int   g_num_neg;
__device__ float g_extra;
__device__ float g_harm[MAX_TRIALS];

// ---------------- Threefry-2x32 (exact JAX partitionable semantics) --------
__device__ __forceinline__ uint32_t rotl32(uint32_t x, int d) {
    return __funnelshift_l(x, x, d);
}

__device__ __forceinline__ uint32_t jax_random_bits32(uint32_t j) {
    const uint32_t k0 = 0u, k1 = 42u;
    const uint32_t ks2 = k0 ^ k1 ^ 0x1BD11BDAu;
    uint32_t x0 = 0u + k0;          // c0 = hi32(j) = 0
    uint32_t x1 = j + k1;           // c1 = lo32(j)
    const int R0[4] = {13, 15, 26, 6};
    const int R1[4] = {17, 29, 16, 24};
#pragma unroll
    for (int i = 0; i < 4; i++) { x0 += x1; x1 = rotl32(x1, R0[i]); x1 ^= x0; }
    x0 += k1;  x1 += ks2 + 1u;
#pragma unroll
    for (int i = 0; i < 4; i++) { x0 += x1; x1 = rotl32(x1, R1[i]); x1 ^= x0; }
    x0 += ks2; x1 += k0 + 2u;
#pragma unroll
    for (int i = 0; i < 4; i++) { x0 += x1; x1 = rotl32(x1, R0[i]); x1 ^= x0; }
    x0 += k0;  x1 += k1 + 3u;
#pragma unroll
    for (int i = 0; i < 4; i++) { x0 += x1; x1 = rotl32(x1, R1[i]); x1 ^= x0; }
    x0 += k1;  x1 += ks2 + 4u;
#pragma unroll
    for (int i = 0; i < 4; i++) { x0 += x1; x1 = rotl32(x1, R0[i]); x1 ^= x0; }
    x0 += ks2; x1 += k0 + 5u;
    return x0 ^ x1;
}

__device__ __forceinline__ float bits_to_uniform(uint32_t bits) {
    return __uint_as_float((bits >> 9) | 0x3f800000u) - 1.0f;
}

__device__ __forceinline__ float sample_neg(uint32_t j, float nnf, int num_neg) {
    float u = bits_to_uniform(jax_random_bits32(j));
    int idx = (int)(u * nnf);
    idx = min(max(idx, 0), num_neg - 1);
    return __ldg(&g_neg_score[idx]);
}

// ---------------- Pass 1: per-block count of label==0 ----------------
__global__ void count_zeros_kernel(const int* __restrict__ labels, int B) {
    int i = blockIdx.x * BLK + threadIdx.x;
    int f = (i < B && labels[i] == 0) ? 1 : 0;
    unsigned m = __ballot_sync(0xffffffffu, f);
    __shared__ int wsum[BLK / 32];
    if ((threadIdx.x & 31) == 0) wsum[threadIdx.x >> 5] = __popc(m);
    __syncthreads();
    if (threadIdx.x == 0) {
        int s = 0;
#pragma unroll
        for (int w = 0; w < BLK / 32; w++) s += wsum[w];
        g_blockcnt[blockIdx.x] = s;
    }
}

// ---------------- Pass 2: exclusive scan + per-replay init -----------------
__global__ void scan_blocks_kernel(int nb) {
    __shared__ int sh[1024];
    int t = threadIdx.x;
    int v[4];
    int base = t * 4;
    int s = 0;
#pragma unroll
    for (int k = 0; k < 4; k++) {
        int idx = base + k;
        v[k] = (idx < nb) ? g_blockcnt[idx] : 0;
        s += v[k];
    }
    sh[t] = s;
    __syncthreads();
    for (int off = 1; off < 1024; off <<= 1) {
        int y = (t >= off) ? sh[t - off] : 0;
        __syncthreads();
        sh[t] += y;
        __syncthreads();
    }
    int run = (t > 0) ? sh[t - 1] : 0;
#pragma unroll
    for (int k = 0; k < 4; k++) {
        int idx = base + k;
        if (idx < nb) {
            int c = v[k];
            g_blockcnt[idx] = run;
            run += c;
        }
    }
    if (t == 0) {
        g_num_neg = sh[1023];
        g_extra = 0.0f;
        float h = 0.0f;
#pragma unroll
        for (int j = 1; j <= MAX_TRIALS; j++) {
            h += __fdiv_rn(1.0f, (float)j);
            g_harm[j - 1] = h;
        }
    }
}

// ---------------- Pass 3: scatter neg scores + pos (idx,score), stable -----
__global__ void scatter_kernel(const int* __restrict__ labels,
                               const float* __restrict__ scores, int B) {
    int i = blockIdx.x * BLK + threadIdx.x;
    int lane = threadIdx.x & 31;
    int w = threadIdx.x >> 5;
    int   lab = (i < B) ? labels[i] : 1;
    float sc  = (i < B) ? scores[i] : 0.0f;
    int f = (i < B && lab == 0) ? 1 : 0;
    unsigned m = __ballot_sync(0xffffffffu, f);
    int wr = __popc(m & ((1u << lane) - 1u));
    __shared__ int woff[BLK / 32];
    if (lane == 0) woff[w] = __popc(m);
    __syncthreads();
    if (threadIdx.x == 0) {
        int r = 0;
#pragma unroll
        for (int k = 0; k < BLK / 32; k++) { int c = woff[k]; woff[k] = r; r += c; }
    }
    __syncthreads();
    if (i < B) {
        int neg_before = g_blockcnt[blockIdx.x] + woff[w] + wr;  // negs strictly before i
        if (f) {
            g_neg_score[neg_before] = sc;
        } else {
            int ps = i - neg_before;
            g_pos_idx[ps] = i;
            g_pos_score[ps] = sc;
        }
    }
}

// ---------------- Main: all trials, fused, one kernel ----------------------
__global__ void main_kernel(int B) {
    __shared__ int   hq[1024];     // heavy items (unresolved after trial 8)
    __shared__ int   hqn;
    __shared__ float red[BLK];
    int tid = threadIdx.x;
    int lane = tid & 31;
    if (tid == 0) hqn = 0;
    __syncthreads();

    int num_neg = g_num_neg;
    int num_pos = B - num_neg;
    float nnf = (float)num_neg;
    float acc = 0.0f;

    if (num_neg > 0) {
        int stride = gridDim.x * blockDim.x * 4;
        for (int base = (blockIdx.x * blockDim.x + tid) * 4; base < num_pos;
             base += stride) {
            int cnt = min(4, num_pos - base);
            uint32_t jb[4];
            float ss[4];
            bool done[4];
#pragma unroll
            for (int k = 0; k < 4; k++) {
                if (k < cnt) {
                    int p = base + k;
                    jb[k] = (uint32_t)__ldg(&g_pos_idx[p]) * (uint32_t)MAX_TRIALS;
                    ss[k] = __ldg(&g_pos_score[p]);
                    done[k] = false;
                } else {
                    jb[k] = 0; ss[k] = 0.0f; done[k] = true;
                }
            }
            // trial 0: batched (MLP-4)
            float ns0[4];
#pragma unroll
            for (int k = 0; k < 4; k++)
                if (!done[k]) ns0[k] = sample_neg(jb[k], nnf, num_neg);
#pragma unroll
            for (int k = 0; k < 4; k++) {
                if (!done[k] && ns0[k] + MARGIN > ss[k]) {
                    acc += __ldg(&g_harm[MAX_TRIALS - 1]) *
                           fmaxf(MARGIN - (ss[k] - ns0[k]), 0.0f);
                    done[k] = true;
                }
            }
            // trials 1..8: interleaved across unresolved items, early exit
            for (int t = 1; t < 9; t++) {
                bool any = false;
#pragma unroll
                for (int k = 0; k < 4; k++) any |= !done[k];
                if (!any) break;
#pragma unroll
                for (int k = 0; k < 4; k++) {
                    if (!done[k]) {
                        float ns = sample_neg(jb[k] + (uint32_t)t, nnf, num_neg);
                        if (ns + MARGIN > ss[k]) {
                            int rank = max(1, MAX_TRIALS / (t + 1));
                            acc += __ldg(&g_harm[rank - 1]) *
                                   fmaxf(MARGIN - (ss[k] - ns), 0.0f);
                            done[k] = true;
                        }
                    }
                }
            }
            // heavies -> block-shared queue
#pragma unroll
            for (int k = 0; k < 4; k++) {
                if (!done[k]) {
                    int h = atomicAdd(&hqn, 1);
                    hq[h] = base + k;
                }
            }
        }
    }
    __syncthreads();

    // heavy items: one warp per item, lanes = trials 9..40, then 41..49
    int nh = hqn;
    int wd = tid >> 5;
    int nw = BLK >> 5;
    for (int h = wd; h < nh; h += nw) {
        int p = hq[h];
        float s = __ldg(&g_pos_score[p]);
        uint32_t jb = (uint32_t)__ldg(&g_pos_idx[p]) * (uint32_t)MAX_TRIALS;

        int t1 = 9 + lane;
        float ns1 = sample_neg(jb + (uint32_t)t1, nnf, num_neg);
        unsigned m1 = __ballot_sync(0xffffffffu, ns1 + MARGIN > s);
        int hit_t = -1;
        float hit_ns = 0.0f;
        if (m1) {
            int lead = __ffs(m1) - 1;
            hit_t = 9 + lead;
            hit_ns = __shfl_sync(0xffffffffu, ns1, lead);
        } else {
            int t2 = 41 + lane;
            bool act = (t2 < MAX_TRIALS);
            float ns2 = act ? sample_neg(jb + (uint32_t)t2, nnf, num_neg) : 0.0f;
            unsigned m2 = __ballot_sync(0xffffffffu, act && (ns2 + MARGIN > s));
            if (m2) {
                int lead = __ffs(m2) - 1;
                hit_t = 41 + lead;
                hit_ns = __shfl_sync(0xffffffffu, ns2, lead);
            }
        }
        if (lane == 0 && hit_t >= 0) {
            int rank = max(1, MAX_TRIALS / (hit_t + 1));
            acc += __ldg(&g_harm[rank - 1]) * fmaxf(MARGIN - (s - hit_ns), 0.0f);
        }
    }

    // block reduction -> one global atomic per block
    red[tid] = acc;
    __syncthreads();
    for (int off = BLK / 2; off > 0; off >>= 1) {
        if (tid < off) red[tid] += red[tid + off];
        __syncthreads();
    }
    if (tid == 0 && red[0] != 0.0f) atomicAdd(&g_extra, red[0]);
}

// ---------------- Finalize (tiny) ------------------------------------------
__global__ void finalize_kernel(float* __restrict__ out, int B) {
    if (threadIdx.x == 0) {
        int nn = g_num_neg;
        int np = B - nn;
        out[0] = (nn > 0 && np > 0) ? g_extra / (float)np : 0.0f;
    }
}

extern "C" void kernel_launch(void* const* d_in, const int* in_sizes, int n_in,
                              void* d_out, int out_size) {
    const float* scores = (const float*)d_in[0];
    const int*   labels = (const int*)d_in[1];
    float* out = (float*)d_out;
    int B  = in_sizes[0];
    int nb = (B + BLK - 1) / BLK;

    count_zeros_kernel<<<nb, BLK>>>(labels, B);
    scan_blocks_kernel<<<1, 1024>>>(nb);
    scatter_kernel<<<nb, BLK>>>(labels, scores, B);
    main_kernel<<<MAIN_GRID, BLK>>>(B);
    finalize_kernel<<<1, 32>>>(out, B);
}

// round 10
// speedup vs baseline: 1.2667x; 1.0912x over previous
#include <cuda_runtime.h>
#include <cstdint>

#define MARGIN 1.0f
#define MAX_TRIALS 50
#define BLK 256
#define MAIN_GRID 1184
#define MAX_B (1 << 20)
#define MAX_NB ((MAX_B + BLK - 1) / BLK)   // 4096

// Scratch (no allocations allowed in kernel_launch)
__device__ float g_neg_score[MAX_B];   // scores of label-0 examples, stable order
__device__ float g_pos_score[MAX_B];   // scores of label-1 examples, stable order
__device__ int   g_pos_idx[MAX_B];     // original indices of label-1 examples
__device__ int   g_blockcnt[MAX_NB];
__device__ int   g_num_neg;
__device__ float g_extra;
__device__ float g_harm[MAX_TRIALS];

// ---------------- Threefry-2x32 (exact JAX partitionable semantics) --------
__device__ __forceinline__ uint32_t rotl32(uint32_t x, int d) {
    return __funnelshift_l(x, x, d);
}

__device__ __forceinline__ uint32_t jax_random_bits32(uint32_t j) {
    const uint32_t k0 = 0u, k1 = 42u;
    const uint32_t ks2 = k0 ^ k1 ^ 0x1BD11BDAu;
    uint32_t x0 = 0u + k0;          // c0 = hi32(j) = 0
    uint32_t x1 = j + k1;           // c1 = lo32(j)
    const int R0[4] = {13, 15, 26, 6};
    const int R1[4] = {17, 29, 16, 24};
#pragma unroll
    for (int i = 0; i < 4; i++) { x0 += x1; x1 = rotl32(x1, R0[i]); x1 ^= x0; }
    x0 += k1;  x1 += ks2 + 1u;
#pragma unroll
    for (int i = 0; i < 4; i++) { x0 += x1; x1 = rotl32(x1, R1[i]); x1 ^= x0; }
    x0 += ks2; x1 += k0 + 2u;
#pragma unroll
    for (int i = 0; i < 4; i++) { x0 += x1; x1 = rotl32(x1, R0[i]); x1 ^= x0; }
    x0 += k0;  x1 += k1 + 3u;
#pragma unroll
    for (int i = 0; i < 4; i++) { x0 += x1; x1 = rotl32(x1, R1[i]); x1 ^= x0; }
    x0 += k1;  x1 += ks2 + 4u;
#pragma unroll
    for (int i = 0; i < 4; i++) { x0 += x1; x1 = rotl32(x1, R0[i]); x1 ^= x0; }
    x0 += ks2; x1 += k0 + 5u;
    return x0 ^ x1;
}

__device__ __forceinline__ float bits_to_uniform(uint32_t bits) {
    return __uint_as_float((bits >> 9) | 0x3f800000u) - 1.0f;
}

__device__ __forceinline__ float sample_neg(uint32_t j, float nnf, int num_neg) {
    float u = bits_to_uniform(jax_random_bits32(j));
    int idx = (int)(u * nnf);
    idx = min(max(idx, 0), num_neg - 1);
    return __ldg(&g_neg_score[idx]);
}

// ---------------- Pass 1: per-block count of label==0 + init ---------------
__global__ void count_zeros_kernel(const int* __restrict__ labels, int B) {
    int i = blockIdx.x * BLK + threadIdx.x;
    int f = (i < B && labels[i] == 0) ? 1 : 0;
    unsigned m = __ballot_sync(0xffffffffu, f);
    __shared__ int wsum[BLK / 32];
    if ((threadIdx.x & 31) == 0) wsum[threadIdx.x >> 5] = __popc(m);
    __syncthreads();
    if (threadIdx.x == 0) {
        int s = 0;
#pragma unroll
        for (int w = 0; w < BLK / 32; w++) s += wsum[w];
        g_blockcnt[blockIdx.x] = s;
        if (blockIdx.x == 0) {
            g_extra = 0.0f;
            float h = 0.0f;
#pragma unroll
            for (int j = 1; j <= MAX_TRIALS; j++) {
                h += __fdiv_rn(1.0f, (float)j);
                g_harm[j - 1] = h;
            }
        }
    }
}

// ---------------- Pass 2: scatter with inline exclusive prefix -------------
__global__ void scatter_kernel(const int* __restrict__ labels,
                               const float* __restrict__ scores, int B, int nb) {
    __shared__ int woff[BLK / 32];
    __shared__ int redi[BLK];
    __shared__ int s_exc, s_bc;
    int bid = blockIdx.x;
    int tid = threadIdx.x;
    int i = bid * BLK + tid;
    int lane = tid & 31;
    int w = tid >> 5;

    int   lab = (i < B) ? labels[i] : 1;
    float sc  = (i < B) ? scores[i] : 0.0f;
    int f = (i < B && lab == 0) ? 1 : 0;
    unsigned m = __ballot_sync(0xffffffffu, f);
    int wr = __popc(m & ((1u << lane) - 1u));
    if (lane == 0) woff[w] = __popc(m);

    // parallel exclusive prefix: sum of g_blockcnt[0..bid)
    int part = 0;
    for (int j = tid; j < bid; j += BLK) part += g_blockcnt[j];
    redi[tid] = part;
    __syncthreads();
    for (int off = BLK / 2; off > 0; off >>= 1) {
        if (tid < off) redi[tid] += redi[tid + off];
        __syncthreads();
    }
    if (tid == 0) {
        s_exc = redi[0];
        int r = 0;
#pragma unroll
        for (int k = 0; k < BLK / 32; k++) { int c = woff[k]; woff[k] = r; r += c; }
        s_bc = r;
    }
    __syncthreads();
    if (bid == nb - 1 && tid == 0) g_num_neg = s_exc + s_bc;

    if (i < B) {
        int neg_before = s_exc + woff[w] + wr;   // negatives strictly before i
        if (f) {
            g_neg_score[neg_before] = sc;
        } else {
            int ps = i - neg_before;
            g_pos_idx[ps] = i;
            g_pos_score[ps] = sc;
        }
    }
}

// ---------------- Main: all trials, fused, one kernel ----------------------
__global__ void main_kernel(int B) {
    __shared__ int   hq[1024];     // heavy items (unresolved after trial 8)
    __shared__ int   hqn;
    __shared__ float red[BLK];
    int tid = threadIdx.x;
    int lane = tid & 31;
    if (tid == 0) hqn = 0;
    __syncthreads();

    int num_neg = g_num_neg;
    int num_pos = B - num_neg;
    float nnf = (float)num_neg;
    float acc = 0.0f;

    if (num_neg > 0) {
        int stride = gridDim.x * blockDim.x * 2;
        for (int base = (blockIdx.x * blockDim.x + tid) * 2; base < num_pos;
             base += stride) {
            int cnt = min(2, num_pos - base);
            uint32_t jb[2];
            float ss[2];
            bool done[2];
#pragma unroll
            for (int k = 0; k < 2; k++) {
                if (k < cnt) {
                    int p = base + k;
                    jb[k] = (uint32_t)__ldg(&g_pos_idx[p]) * (uint32_t)MAX_TRIALS;
                    ss[k] = __ldg(&g_pos_score[p]);
                    done[k] = false;
                } else {
                    jb[k] = 0; ss[k] = 0.0f; done[k] = true;
                }
            }
            // trial 0: batched (MLP-2)
            float ns0[2];
#pragma unroll
            for (int k = 0; k < 2; k++)
                if (!done[k]) ns0[k] = sample_neg(jb[k], nnf, num_neg);
#pragma unroll
            for (int k = 0; k < 2; k++) {
                if (!done[k] && ns0[k] + MARGIN > ss[k]) {
                    acc += __ldg(&g_harm[MAX_TRIALS - 1]) *
                           fmaxf(MARGIN - (ss[k] - ns0[k]), 0.0f);
                    done[k] = true;
                }
            }
            // trials 1..8: interleaved across unresolved items, early exit
            for (int t = 1; t < 9; t++) {
                bool any = false;
#pragma unroll
                for (int k = 0; k < 2; k++) any |= !done[k];
                if (!any) break;
#pragma unroll
                for (int k = 0; k < 2; k++) {
                    if (!done[k]) {
                        float ns = sample_neg(jb[k] + (uint32_t)t, nnf, num_neg);
                        if (ns + MARGIN > ss[k]) {
                            int rank = max(1, MAX_TRIALS / (t + 1));
                            acc += __ldg(&g_harm[rank - 1]) *
                                   fmaxf(MARGIN - (ss[k] - ns), 0.0f);
                            done[k] = true;
                        }
                    }
                }
            }
            // heavies -> block-shared queue
#pragma unroll
            for (int k = 0; k < 2; k++) {
                if (!done[k]) {
                    int h = atomicAdd(&hqn, 1);
                    hq[h] = base + k;
                }
            }
        }
    }
    __syncthreads();

    // heavy items: one warp per item, lanes = trials 9..40, then 41..49
    int nh = hqn;
    int wd = tid >> 5;
    int nw = BLK >> 5;
    for (int h = wd; h < nh; h += nw) {
        int p = hq[h];
        float s = __ldg(&g_pos_score[p]);
        uint32_t jb = (uint32_t)__ldg(&g_pos_idx[p]) * (uint32_t)MAX_TRIALS;

        int t1 = 9 + lane;
        float ns1 = sample_neg(jb + (uint32_t)t1, nnf, num_neg);
        unsigned m1 = __ballot_sync(0xffffffffu, ns1 + MARGIN > s);
        int hit_t = -1;
        float hit_ns = 0.0f;
        if (m1) {
            int lead = __ffs(m1) - 1;
            hit_t = 9 + lead;
            hit_ns = __shfl_sync(0xffffffffu, ns1, lead);
        } else {
            int t2 = 41 + lane;
            bool act = (t2 < MAX_TRIALS);
            float ns2 = act ? sample_neg(jb + (uint32_t)t2, nnf, num_neg) : 0.0f;
            unsigned m2 = __ballot_sync(0xffffffffu, act && (ns2 + MARGIN > s));
            if (m2) {
                int lead = __ffs(m2) - 1;
                hit_t = 41 + lead;
                hit_ns = __shfl_sync(0xffffffffu, ns2, lead);
            }
        }
        if (lane == 0 && hit_t >= 0) {
            int rank = max(1, MAX_TRIALS / (hit_t + 1));
            acc += __ldg(&g_harm[rank - 1]) * fmaxf(MARGIN - (s - hit_ns), 0.0f);
        }
    }

    // block reduction -> one global atomic per block
    red[tid] = acc;
    __syncthreads();
    for (int off = BLK / 2; off > 0; off >>= 1) {
        if (tid < off) red[tid] += red[tid + off];
        __syncthreads();
    }
    if (tid == 0 && red[0] != 0.0f) atomicAdd(&g_extra, red[0]);
}

// ---------------- Finalize (tiny) ------------------------------------------
__global__ void finalize_kernel(float* __restrict__ out, int B) {
    if (threadIdx.x == 0) {
        int nn = g_num_neg;
        int np = B - nn;
        out[0] = (nn > 0 && np > 0) ? g_extra / (float)np : 0.0f;
    }
}

extern "C" void kernel_launch(void* const* d_in, const int* in_sizes, int n_in,
                              void* d_out, int out_size) {
    const float* scores = (const float*)d_in[0];
    const int*   labels = (const int*)d_in[1];
    float* out = (float*)d_out;
    int B  = in_sizes[0];
    int nb = (B + BLK - 1) / BLK;

    count_zeros_kernel<<<nb, BLK>>>(labels, B);
    scatter_kernel<<<nb, BLK>>>(labels, scores, B, nb);
    main_kernel<<<MAIN_GRID, BLK>>>(B);
    finalize_kernel<<<1, 32>>>(out, B);
}

// round 11
// speedup vs baseline: 1.3483x; 1.0644x over previous
#include <cuda_runtime.h>
#include <cstdint>

#define MARGIN 1.0f
#define MAX_TRIALS 50
#define BLK 256
#define MAIN_GRID 1184
#define MAX_B (1 << 20)
#define VEC_NB (MAX_B / (BLK * 4))         // 1024 blocks for vectorized prepasses

// Scratch (no allocations allowed in kernel_launch)
__device__ float g_neg_score[MAX_B];   // scores of label-0 examples, stable order
__device__ float g_pos_score[MAX_B];   // scores of label-1 examples, stable order
__device__ int   g_pos_idx[MAX_B];     // original indices of label-1 examples
__device__ int   g_blockcnt[VEC_NB];
__device__ int   g_num_neg;
__device__ int   g_done;
__device__ float g_extra;
__device__ float g_harm[MAX_TRIALS];

// ---------------- Threefry-2x32 (exact JAX partitionable semantics) --------
__device__ __forceinline__ uint32_t rotl32(uint32_t x, int d) {
    return __funnelshift_l(x, x, d);
}

__device__ __forceinline__ uint32_t jax_random_bits32(uint32_t j) {
    const uint32_t k0 = 0u, k1 = 42u;
    const uint32_t ks2 = k0 ^ k1 ^ 0x1BD11BDAu;
    uint32_t x0 = 0u + k0;          // c0 = hi32(j) = 0
    uint32_t x1 = j + k1;           // c1 = lo32(j)
    const int R0[4] = {13, 15, 26, 6};
    const int R1[4] = {17, 29, 16, 24};
#pragma unroll
    for (int i = 0; i < 4; i++) { x0 += x1; x1 = rotl32(x1, R0[i]); x1 ^= x0; }
    x0 += k1;  x1 += ks2 + 1u;
#pragma unroll
    for (int i = 0; i < 4; i++) { x0 += x1; x1 = rotl32(x1, R1[i]); x1 ^= x0; }
    x0 += ks2; x1 += k0 + 2u;
#pragma unroll
    for (int i = 0; i < 4; i++) { x0 += x1; x1 = rotl32(x1, R0[i]); x1 ^= x0; }
    x0 += k0;  x1 += k1 + 3u;
#pragma unroll
    for (int i = 0; i < 4; i++) { x0 += x1; x1 = rotl32(x1, R1[i]); x1 ^= x0; }
    x0 += k1;  x1 += ks2 + 4u;
#pragma unroll
    for (int i = 0; i < 4; i++) { x0 += x1; x1 = rotl32(x1, R0[i]); x1 ^= x0; }
    x0 += ks2; x1 += k0 + 5u;
    return x0 ^ x1;
}

__device__ __forceinline__ float bits_to_uniform(uint32_t bits) {
    return __uint_as_float((bits >> 9) | 0x3f800000u) - 1.0f;
}

__device__ __forceinline__ float sample_neg(uint32_t j, float nnf, int num_neg) {
    float u = bits_to_uniform(jax_random_bits32(j));
    int idx = (int)(u * nnf);
    idx = min(max(idx, 0), num_neg - 1);
    return __ldg(&g_neg_score[idx]);
}

// ---------------- Pass 1: vec4 per-block count of label==0 + init ----------
// Each block covers 1024 elements (256 threads x int4). B is a multiple of 4.
__global__ void count_zeros_kernel(const int* __restrict__ labels, int B) {
    int tid = threadIdx.x;
    int e0 = (blockIdx.x * BLK + tid) * 4;
    int c = 0;
    if (e0 + 3 < B) {
        int4 lv = __ldg((const int4*)(labels + e0));
        c = (lv.x == 0) + (lv.y == 0) + (lv.z == 0) + (lv.w == 0);
    } else {
        for (int k = 0; k < 4; k++)
            if (e0 + k < B && labels[e0 + k] == 0) c++;
    }
#pragma unroll
    for (int off = 16; off > 0; off >>= 1)
        c += __shfl_down_sync(0xffffffffu, c, off);
    __shared__ int wsum[BLK / 32];
    if ((tid & 31) == 0) wsum[tid >> 5] = c;
    __syncthreads();
    if (tid == 0) {
        int s = 0;
#pragma unroll
        for (int w = 0; w < BLK / 32; w++) s += wsum[w];
        g_blockcnt[blockIdx.x] = s;
        if (blockIdx.x == 0) {
            g_extra = 0.0f;
            float h = 0.0f;
#pragma unroll
            for (int j = 1; j <= MAX_TRIALS; j++) {
                h += __fdiv_rn(1.0f, (float)j);
                g_harm[j - 1] = h;
            }
        }
    }
}

// ---------------- Pass 2: vec4 scatter with inline exclusive prefix --------
__global__ void scatter_kernel(const int* __restrict__ labels,
                               const float* __restrict__ scores, int B, int nb) {
    __shared__ int wtot[BLK / 32];
    __shared__ int redi[BLK];
    __shared__ int s_exc;
    int bid = blockIdx.x;
    int tid = threadIdx.x;
    int lane = tid & 31;
    int w = tid >> 5;
    int e0 = (bid * BLK + tid) * 4;

    int   lab[4];
    float sc[4];
    if (e0 + 3 < B) {
        int4   lv = __ldg((const int4*)(labels + e0));
        float4 sv = __ldg((const float4*)(scores + e0));
        lab[0] = lv.x; lab[1] = lv.y; lab[2] = lv.z; lab[3] = lv.w;
        sc[0] = sv.x; sc[1] = sv.y; sc[2] = sv.z; sc[3] = sv.w;
    } else {
        for (int k = 0; k < 4; k++) {
            lab[k] = (e0 + k < B) ? labels[e0 + k] : 1;
            sc[k]  = (e0 + k < B) ? scores[e0 + k] : 0.0f;
        }
    }
    int f[4], c = 0;
#pragma unroll
    for (int k = 0; k < 4; k++) { f[k] = (e0 + k < B && lab[k] == 0) ? 1 : 0; c += f[k]; }

    // warp inclusive scan of per-thread counts
    int incl = c;
#pragma unroll
    for (int off = 1; off < 32; off <<= 1) {
        int y = __shfl_up_sync(0xffffffffu, incl, off);
        if (lane >= off) incl += y;
    }
    int thr_exc = incl - c;                 // zeros before this thread within warp
    if (lane == 31) wtot[w] = incl;

    // block prefix: sum of g_blockcnt[0..bid)  (nb <= 1024, <=4 loads/thread)
    int part = 0;
    for (int j = tid; j < bid; j += BLK) part += g_blockcnt[j];
    redi[tid] = part;
    __syncthreads();
    for (int off = BLK / 2; off > 0; off >>= 1) {
        if (tid < off) redi[tid] += redi[tid + off];
        __syncthreads();
    }
    __shared__ int woff[BLK / 32];
    if (tid == 0) {
        s_exc = redi[0];
        int r = 0;
#pragma unroll
        for (int k = 0; k < BLK / 32; k++) { int t = wtot[k]; woff[k] = r; r += t; }
        if (bid == nb - 1) g_num_neg = s_exc + r;
    }
    __syncthreads();

    int neg_before = s_exc + woff[w] + thr_exc;   // zeros strictly before e0
#pragma unroll
    for (int k = 0; k < 4; k++) {
        int i = e0 + k;
        if (i < B) {
            if (f[k]) {
                g_neg_score[neg_before] = sc[k];
            } else {
                int ps = i - neg_before;
                g_pos_idx[ps] = i;
                g_pos_score[ps] = sc[k];
            }
        }
        neg_before += f[k];
    }
}

// ---------------- Main: all trials + finalize, one kernel ------------------
__global__ void main_kernel(float* __restrict__ out, int B) {
    __shared__ int   hq[1024];     // heavy items (unresolved after trial 8)
    __shared__ int   hqn;
    __shared__ float red[BLK];
    __shared__ bool  s_last;
    int tid = threadIdx.x;
    int lane = tid & 31;
    if (tid == 0) hqn = 0;
    __syncthreads();

    int num_neg = g_num_neg;
    int num_pos = B - num_neg;
    float nnf = (float)num_neg;
    float acc = 0.0f;

    if (num_neg > 0) {
        int stride = gridDim.x * blockDim.x * 2;
        for (int base = (blockIdx.x * blockDim.x + tid) * 2; base < num_pos;
             base += stride) {
            int cnt = min(2, num_pos - base);
            uint32_t jb[2];
            float ss[2];
            bool done[2];
#pragma unroll
            for (int k = 0; k < 2; k++) {
                if (k < cnt) {
                    int p = base + k;
                    jb[k] = (uint32_t)__ldg(&g_pos_idx[p]) * (uint32_t)MAX_TRIALS;
                    ss[k] = __ldg(&g_pos_score[p]);
                    done[k] = false;
                } else {
                    jb[k] = 0; ss[k] = 0.0f; done[k] = true;
                }
            }
            // trial 0: batched (MLP-2)
            float ns0[2];
#pragma unroll
            for (int k = 0; k < 2; k++)
                if (!done[k]) ns0[k] = sample_neg(jb[k], nnf, num_neg);
#pragma unroll
            for (int k = 0; k < 2; k++) {
                if (!done[k] && ns0[k] + MARGIN > ss[k]) {
                    acc += __ldg(&g_harm[MAX_TRIALS - 1]) *
                           fmaxf(MARGIN - (ss[k] - ns0[k]), 0.0f);
                    done[k] = true;
                }
            }
            // trials 1..8: interleaved across unresolved items, early exit
            for (int t = 1; t < 9; t++) {
                bool any = false;
#pragma unroll
                for (int k = 0; k < 2; k++) any |= !done[k];
                if (!any) break;
#pragma unroll
                for (int k = 0; k < 2; k++) {
                    if (!done[k]) {
                        float ns = sample_neg(jb[k] + (uint32_t)t, nnf, num_neg);
                        if (ns + MARGIN > ss[k]) {
                            int rank = max(1, MAX_TRIALS / (t + 1));
                            acc += __ldg(&g_harm[rank - 1]) *
                                   fmaxf(MARGIN - (ss[k] - ns), 0.0f);
                            done[k] = true;
                        }
                    }
                }
            }
            // heavies -> block-shared queue
#pragma unroll
            for (int k = 0; k < 2; k++) {
                if (!done[k]) {
                    int h = atomicAdd(&hqn, 1);
                    hq[h] = base + k;
                }
            }
        }
    }
    __syncthreads();

    // heavy items: one warp per item, lanes = trials 9..40, then 41..49
    int nh = hqn;
    int wd = tid >> 5;
    int nw = BLK >> 5;
    for (int h = wd; h < nh; h += nw) {
        int p = hq[h];
        float s = __ldg(&g_pos_score[p]);
        uint32_t jb = (uint32_t)__ldg(&g_pos_idx[p]) * (uint32_t)MAX_TRIALS;

        int t1 = 9 + lane;
        float ns1 = sample_neg(jb + (uint32_t)t1, nnf, num_neg);
        unsigned m1 = __ballot_sync(0xffffffffu, ns1 + MARGIN > s);
        int hit_t = -1;
        float hit_ns = 0.0f;
        if (m1) {
            int lead = __ffs(m1) - 1;
            hit_t = 9 + lead;
            hit_ns = __shfl_sync(0xffffffffu, ns1, lead);
        } else {
            int t2 = 41 + lane;
            bool act = (t2 < MAX_TRIALS);
            float ns2 = act ? sample_neg(jb + (uint32_t)t2, nnf, num_neg) : 0.0f;
            unsigned m2 = __ballot_sync(0xffffffffu, act && (ns2 + MARGIN > s));
            if (m2) {
                int lead = __ffs(m2) - 1;
                hit_t = 41 + lead;
                hit_ns = __shfl_sync(0xffffffffu, ns2, lead);
            }
        }
        if (lane == 0 && hit_t >= 0) {
            int rank = max(1, MAX_TRIALS / (hit_t + 1));
            acc += __ldg(&g_harm[rank - 1]) * fmaxf(MARGIN - (s - hit_ns), 0.0f);
        }
    }

    // block reduction -> one global atomic per block
    red[tid] = acc;
    __syncthreads();
    for (int off = BLK / 2; off > 0; off >>= 1) {
        if (tid < off) red[tid] += red[tid + off];
        __syncthreads();
    }
    if (tid == 0) {
        if (red[0] != 0.0f) atomicAdd(&g_extra, red[0]);
        __threadfence();
        int t = atomicAdd(&g_done, 1);
        s_last = (t == gridDim.x - 1);
    }
    __syncthreads();

    // last block finalizes
    if (s_last && tid == 0) {
        int np = num_pos;
        out[0] = (num_neg > 0 && np > 0) ? g_extra / (float)np : 0.0f;
        g_done = 0;                       // reset for next graph replay
    }
}

extern "C" void kernel_launch(void* const* d_in, const int* in_sizes, int n_in,
                              void* d_out, int out_size) {
    const float* scores = (const float*)d_in[0];
    const int*   labels = (const int*)d_in[1];
    float* out = (float*)d_out;
    int B  = in_sizes[0];
    int nb = (B + BLK * 4 - 1) / (BLK * 4);

    count_zeros_kernel<<<nb, BLK>>>(labels, B);
    scatter_kernel<<<nb, BLK>>>(labels, scores, B, nb);
    main_kernel<<<MAIN_GRID, BLK>>>(out, B);
}